// round 14
// baseline (speedup 1.0000x reference)
#include <cuda_runtime.h>
#include <cuda_fp16.h>
#include <stdint.h>
#include <math.h>

#define NB 1024

__device__ __align__(16) __half g_Wh[131072];  // W1|W2|W3 row-major [FIN][FOUT], fp16

// ---- smem layout (bytes) ----
#define OFF_DINV 1024
#define OFF_MSK  3584        // mask fp16 [128][136]
#define OFF_HHI  38400       // H fp16 [128][264]
#define OFF_T    105984      // T fp16 [128][264] (separate from H!)
#define OFF_W    173568      // 2 x Whi[32][264]
#define WBUF     16896
#define SMEM_SZ  207360
#define SH 264
#define SM 136
#define SW 264

__device__ __forceinline__ uint32_t s2u(const void* p) {
    uint32_t a;
    asm("{ .reg .u64 t; cvta.to.shared.u64 t, %1; cvt.u32.u64 %0, t; }" : "=r"(a) : "l"(p));
    return a;
}
__device__ __forceinline__ unsigned pk(float a, float b) {   // lo=a, hi=b
    __half2 h = __floats2half2_rn(a, b);
    return *(unsigned*)&h;
}
__device__ __forceinline__ float elu_neg(float v) { return __expf(v) - 1.0f; }
__device__ __forceinline__ void ldsm4(uint32_t* r, uint32_t a) {
    asm volatile("ldmatrix.sync.aligned.m8n8.x4.shared.b16 {%0,%1,%2,%3}, [%4];"
                 : "=r"(r[0]), "=r"(r[1]), "=r"(r[2]), "=r"(r[3]) : "r"(a));
}
__device__ __forceinline__ void ldsm4t(uint32_t* r, uint32_t a) {
    asm volatile("ldmatrix.sync.aligned.m8n8.x4.trans.shared.b16 {%0,%1,%2,%3}, [%4];"
                 : "=r"(r[0]), "=r"(r[1]), "=r"(r[2]), "=r"(r[3]) : "r"(a));
}
__device__ __forceinline__ void mma16816(float* c, const uint32_t* a, uint32_t b0, uint32_t b1) {
    asm volatile(
        "mma.sync.aligned.m16n8k16.row.col.f32.f16.f16.f32 "
        "{%0,%1,%2,%3}, {%4,%5,%6,%7}, {%8,%9}, {%0,%1,%2,%3};"
        : "+f"(c[0]), "+f"(c[1]), "+f"(c[2]), "+f"(c[3])
        : "r"(a[0]), "r"(a[1]), "r"(a[2]), "r"(a[3]), "r"(b0), "r"(b1));
}
__device__ __forceinline__ void cp16(uint32_t s, const void* g) {
    unsigned long long ga = (unsigned long long)__cvta_generic_to_global(g);
    asm volatile("cp.async.ca.shared.global [%0], [%1], 16;" :: "r"(s), "l"(ga) : "memory");
}
#define CP_COMMIT asm volatile("cp.async.commit_group;" ::: "memory")
#define CP_WAIT0  asm volatile("cp.async.wait_group 0;" ::: "memory")
#define GRP_BAR(wn) asm volatile("bar.sync %0, %1;" :: "r"((wn) + 1), "r"(128) : "memory")

// group-private staging: 32 W rows, this group's NWN-col quarter
template <int FOUT>
__device__ __forceinline__ void stageW_grp(uint32_t sb, int wn, int gtid,
                                           int wbase, int kb, int buf) {
    constexpr int NWN = FOUT / 4;
    constexpr int cnt = 32 * NWN / 8;
    for (int i = gtid; i < cnt; i += 128) {
        int r = i / (NWN / 8), c8 = wn * NWN + (i % (NWN / 8)) * 8;
        size_t go = (size_t)wbase + (size_t)(kb * 32 + r) * FOUT + c8;
        cp16(sb + OFF_W + buf * WBUF + (uint32_t)(r * SW + c8) * 2, g_Wh + go);
    }
}

// ---------------- prep: W fp16 row-major images ----------------
__global__ __launch_bounds__(256) void prep_w(const float* __restrict__ W1,
                                              const float* __restrict__ W2,
                                              const float* __restrict__ W3) {
    int id = blockIdx.x * 256 + threadIdx.x;   // 131072
    const float* W; int base, l;
    if (id < 32768)      { W = W1; base = 0;     l = id; }
    else if (id < 98304) { W = W2; base = 32768; l = id - 32768; }
    else                 { W = W3; base = 98304; l = id - 98304; }
    g_Wh[base + l] = __float2half_rn(W[l]);
}

// ---------------- one layer (first W block already prefetched) ----------------
template <int FIN, int FOUT, bool ELU, bool LAST, int NEXT_FOUT, int NEXT_WBASE>
__device__ __forceinline__ void layer(char* smem, uint32_t sb, const float* __restrict__ bias,
                                      int wbase, float* __restrict__ outg, int b) {
    const int tid = threadIdx.x, lane = tid & 31, wid = tid >> 5;
    const int wm = wid >> 2, wn = wid & 3;               // 4 x 4 warp grid
    const int gtid = wm * 32 + lane;                     // group-local tid (128/group)
    constexpr int NWN = FOUT / 4, NT16 = NWN / 16, NT8 = NWN / 8, KB = FIN / 32;

    const float* sDinv = (const float*)(smem + OFF_DINV);

    float acc[2][NT8][4];
#pragma unroll
    for (int m = 0; m < 2; ++m)
#pragma unroll
        for (int i = 0; i < NT8; ++i)
#pragma unroll
            for (int q = 0; q < 4; ++q) acc[m][i][q] = 0.0f;

    // first W block prefetched by previous layer (or kernel prologue)
    CP_WAIT0;
    GRP_BAR(wn);

    const uint32_t aRow  = (uint32_t)(wm * 32 + (lane & 15));
    const uint32_t aCol8 = (uint32_t)((lane >> 4) * 8);
    const uint32_t bRow  = (uint32_t)((lane & 7) + ((lane >> 3) & 1) * 8);
    const uint32_t bCol8 = (uint32_t)((lane >> 4) * 8);

    // ---- GEMM1: T = H @ W (H read-only; W group-private ring) ----
    for (int kb = 0; kb < KB; ++kb) {
        if (kb + 1 < KB) stageW_grp<FOUT>(sb, wn, gtid, wbase, kb + 1, (kb + 1) & 1);
        CP_COMMIT;
        uint32_t wb = sb + OFF_W + (kb & 1) * WBUF;
#pragma unroll
        for (int ks = 0; ks < 2; ++ks) {
            const int k = kb * 2 + ks;
            uint32_t ah[2][4];
#pragma unroll
            for (int m = 0; m < 2; ++m)
                ldsm4(ah[m], sb + OFF_HHI + ((aRow + 16 * m) * SH + k * 16 + aCol8) * 2);
            uint32_t bh[NT16][4];
#pragma unroll
            for (int t = 0; t < NT16; ++t)
                ldsm4t(bh[t], wb + ((ks * 16 + bRow) * SW + wn * NWN + t * 16 + bCol8) * 2);
#pragma unroll
            for (int t = 0; t < NT16; ++t)
#pragma unroll
                for (int m = 0; m < 2; ++m) {
                    mma16816(acc[m][2 * t], ah[m], bh[t][0], bh[t][1]);
                    mma16816(acc[m][2 * t + 1], ah[m], bh[t][2], bh[t][3]);
                }
        }
        CP_WAIT0;
        GRP_BAR(wn);
    }

    // prefetch NEXT layer's first W block (group quarter; ring idle for this group)
    if constexpr (NEXT_FOUT > 0) {
        stageW_grp<NEXT_FOUT>(sb, wn, gtid, NEXT_WBASE, 0, 0);
        CP_COMMIT;
    }

    // ---- epilogue1: T * dinv_row -> separate T buffer (group cols) ----
#pragma unroll
    for (int m = 0; m < 2; ++m) {
        int r0 = wm * 32 + m * 16 + (lane >> 2), r1 = r0 + 8;
        float d0 = sDinv[r0], d1 = sDinv[r1];
#pragma unroll
        for (int i = 0; i < NT8; ++i) {
            int col = wn * NWN + i * 8 + (lane & 3) * 2;
            *(unsigned*)(smem + OFF_T + (r0 * SH + col) * 2) =
                pk(acc[m][i][0] * d0, acc[m][i][1] * d0);
            *(unsigned*)(smem + OFF_T + (r1 * SH + col) * 2) =
                pk(acc[m][i][2] * d1, acc[m][i][3] * d1);
        }
    }
    GRP_BAR(wn);   // T quarter complete for this group

    // ---- GEMM2: out = Mask @ T (group column quarter) ----
    float ac2[2][NT8][4];
#pragma unroll
    for (int m = 0; m < 2; ++m)
#pragma unroll
        for (int i = 0; i < NT8; ++i)
#pragma unroll
            for (int q = 0; q < 4; ++q) ac2[m][i][q] = 0.0f;

#pragma unroll
    for (int k = 0; k < 8; ++k) {
        uint32_t am[2][4];
#pragma unroll
        for (int m = 0; m < 2; ++m)
            ldsm4(am[m], sb + OFF_MSK + ((aRow + 16 * m) * SM + k * 16 + aCol8) * 2);
        uint32_t th[NT16][4];
#pragma unroll
        for (int t = 0; t < NT16; ++t)
            ldsm4t(th[t], sb + OFF_T + ((k * 16 + bRow) * SH + wn * NWN + t * 16 + bCol8) * 2);
#pragma unroll
        for (int t = 0; t < NT16; ++t)
#pragma unroll
            for (int m = 0; m < 2; ++m) {
                mma16816(ac2[m][2 * t], am[m], th[t][0], th[t][1]);
                mma16816(ac2[m][2 * t + 1], am[m], th[t][2], th[t][3]);
            }
    }
    // full sync: epi2 overwrites H, which lagging groups' GEMM1 still reads
    __syncthreads();

    // ---- epilogue2: *dinv_i + bias(ldg), ELU, write next-H or global out ----
#pragma unroll
    for (int m = 0; m < 2; ++m) {
        int r0 = wm * 32 + m * 16 + (lane >> 2), r1 = r0 + 8;
        float d0 = sDinv[r0], d1 = sDinv[r1];
#pragma unroll
        for (int i = 0; i < NT8; ++i) {
            int col = wn * NWN + i * 8 + (lane & 3) * 2;
            float2 bv = __ldg((const float2*)(bias + col));
            float v00 = fmaf(ac2[m][i][0], d0, bv.x), v01 = fmaf(ac2[m][i][1], d0, bv.y);
            float v10 = fmaf(ac2[m][i][2], d1, bv.x), v11 = fmaf(ac2[m][i][3], d1, bv.y);
            if (ELU) {
                v00 = v00 > 0.f ? v00 : elu_neg(v00);
                v01 = v01 > 0.f ? v01 : elu_neg(v01);
                v10 = v10 > 0.f ? v10 : elu_neg(v10);
                v11 = v11 > 0.f ? v11 : elu_neg(v11);
            }
            if (LAST) {
                *(float2*)(outg + ((size_t)b * 128 + r0) * 128 + col) = make_float2(v00, v01);
                *(float2*)(outg + ((size_t)b * 128 + r1) * 128 + col) = make_float2(v10, v11);
            } else {
                *(unsigned*)(smem + OFF_HHI + (r0 * SH + col) * 2) = pk(v00, v01);
                *(unsigned*)(smem + OFF_HHI + (r1 * SH + col) * 2) = pk(v10, v11);
            }
        }
    }
    __syncthreads();   // next layer's GEMM1 reads all of H
}

// ---------------- fused kernel ----------------
__global__ void __launch_bounds__(512, 1) gcn_fused(
    const float* __restrict__ x, const float* __restrict__ adj,
    const float* __restrict__ b1, const float* __restrict__ b2,
    const float* __restrict__ b3, float* __restrict__ out) {
    extern __shared__ char smem[];
    const uint32_t sb = s2u(smem);
    const int b = blockIdx.x, tid = threadIdx.x;
    const int warp = tid >> 5, lane = tid & 31;
    const int wm = warp >> 2, wn = warp & 3;
    const int gtid = wm * 32 + lane;

    // prefetch layer-1's first W block (group quarter) under the prologue
    stageW_grp<256>(sb, wn, gtid, 0, 0, 0);
    CP_COMMIT;

    // build dinv + fp16 mask matrix straight from ballots
    float* sDinv = (float*)(smem + OFF_DINV);
    const float* ab = adj + (size_t)b * 16384;
    for (int r = warp; r < 128; r += 16) {
        const float* a = ab + r * 128;
        unsigned m[4]; int deg = 0;
#pragma unroll
        for (int s = 0; s < 4; ++s) {
            unsigned w = __ballot_sync(0xffffffffu, a[lane + 32 * s] != 0.0f);
            if (s == (r >> 5)) w |= 1u << (r & 31);
            m[s] = w; deg += __popc(w);
        }
        if (lane == 0) sDinv[r] = rsqrtf((float)deg);
        unsigned w = m[lane >> 3];
        int s4 = (lane & 7) * 4;
        unsigned u0 = (((w >> s4) & 1u) ? 0x3C00u : 0u) | (((w >> (s4 + 1)) & 1u) ? 0x3C000000u : 0u);
        unsigned u1 = (((w >> (s4 + 2)) & 1u) ? 0x3C00u : 0u) | (((w >> (s4 + 3)) & 1u) ? 0x3C000000u : 0u);
        *(uint2*)(smem + OFF_MSK + (r * SM + lane * 4) * 2) = make_uint2(u0, u1);
    }

    // stage x as fp16
    const float* xb = x + (size_t)b * 16384;
    for (int idx = tid; idx < 8192; idx += 512) {
        int r = idx >> 6, c2 = (idx & 63) * 2;
        *(unsigned*)(smem + OFF_HHI + (r * SH + c2) * 2) =
            pk(xb[r * 128 + c2], xb[r * 128 + c2 + 1]);
    }
    __syncthreads();

    layer<128, 256, true,  false, 256, 32768>(smem, sb, b1, 0,     out, b);
    layer<256, 256, true,  false, 128, 98304>(smem, sb, b2, 32768, out, b);
    layer<256, 128, false, true,  0,   0    >(smem, sb, b3, 98304, out, b);
}

// ---------------------------------------------------------------------------
extern "C" void kernel_launch(void* const* d_in, const int* in_sizes, int n_in,
                              void* d_out, int out_size) {
    const float* x   = (const float*)d_in[0];
    const float* adj = (const float*)d_in[1];
    const float* W1  = (const float*)d_in[2];
    const float* b1  = (const float*)d_in[3];
    const float* W2  = (const float*)d_in[4];
    const float* b2  = (const float*)d_in[5];
    const float* W3  = (const float*)d_in[6];
    const float* b3  = (const float*)d_in[7];
    float* out = (float*)d_out;

    cudaFuncSetAttribute(gcn_fused, cudaFuncAttributeMaxDynamicSharedMemorySize, SMEM_SZ);
    prep_w<<<512, 256>>>(W1, W2, W3);
    gcn_fused<<<NB, 512, SMEM_SZ>>>(x, adj, b1, b2, b3, out);
}

// round 15
// speedup vs baseline: 1.0678x; 1.0678x over previous
#include <cuda_runtime.h>
#include <cuda_fp16.h>
#include <stdint.h>
#include <math.h>

#define NB 1024

__device__ __align__(16) __half g_Wh[131072];  // W1|W2|W3 row-major [FIN][FOUT], fp16

// ---- smem layout (bytes) ----
#define OFF_BIAS 0
#define OFF_DINV 1024
#define OFF_MSK  3584        // mask fp16 [128][136] (built once, layer-invariant)
#define OFF_HHI  38400       // H/T fp16 [128][264]
#define OFF_W    105984      // 2 x Whi[64][264]
#define WBUF     33792
#define SMEM_SZ  173568
#define SH 264
#define SM 136
#define SW 264

__device__ __forceinline__ uint32_t s2u(const void* p) {
    uint32_t a;
    asm("{ .reg .u64 t; cvta.to.shared.u64 t, %1; cvt.u32.u64 %0, t; }" : "=r"(a) : "l"(p));
    return a;
}
__device__ __forceinline__ unsigned pk(float a, float b) {   // lo=a, hi=b
    __half2 h = __floats2half2_rn(a, b);
    return *(unsigned*)&h;
}
__device__ __forceinline__ float elu_neg(float v) { return __expf(v) - 1.0f; }
__device__ __forceinline__ void ldsm4(uint32_t* r, uint32_t a) {
    asm volatile("ldmatrix.sync.aligned.m8n8.x4.shared.b16 {%0,%1,%2,%3}, [%4];"
                 : "=r"(r[0]), "=r"(r[1]), "=r"(r[2]), "=r"(r[3]) : "r"(a));
}
__device__ __forceinline__ void ldsm4t(uint32_t* r, uint32_t a) {
    asm volatile("ldmatrix.sync.aligned.m8n8.x4.trans.shared.b16 {%0,%1,%2,%3}, [%4];"
                 : "=r"(r[0]), "=r"(r[1]), "=r"(r[2]), "=r"(r[3]) : "r"(a));
}
__device__ __forceinline__ void mma16816(float* c, const uint32_t* a, uint32_t b0, uint32_t b1) {
    asm volatile(
        "mma.sync.aligned.m16n8k16.row.col.f32.f16.f16.f32 "
        "{%0,%1,%2,%3}, {%4,%5,%6,%7}, {%8,%9}, {%0,%1,%2,%3};"
        : "+f"(c[0]), "+f"(c[1]), "+f"(c[2]), "+f"(c[3])
        : "r"(a[0]), "r"(a[1]), "r"(a[2]), "r"(a[3]), "r"(b0), "r"(b1));
}
__device__ __forceinline__ void cp16(uint32_t s, const void* g) {
    unsigned long long ga = (unsigned long long)__cvta_generic_to_global(g);
    asm volatile("cp.async.ca.shared.global [%0], [%1], 16;" :: "r"(s), "l"(ga) : "memory");
}
#define CP_COMMIT asm volatile("cp.async.commit_group;" ::: "memory")
#define CP_WAIT0  asm volatile("cp.async.wait_group 0;" ::: "memory")
#define GRP_BAR(wn) asm volatile("bar.sync %0, %1;" :: "r"((wn) + 1), "r"(128) : "memory")

// stage one 64-row W block into ring buffer `buf` (full-CTA, coalesced rows)
template <int FOUT>
__device__ __forceinline__ void stageW(uint32_t sb, int tid, int wbase, int kb, int buf) {
    const int cnt = 64 * FOUT / 8;
    for (int i = tid; i < cnt; i += 512) {
        int r = i / (FOUT / 8), c8 = (i % (FOUT / 8)) * 8;
        size_t go = (size_t)wbase + (size_t)(kb * 64 + r) * FOUT + c8;
        cp16(sb + OFF_W + buf * WBUF + (uint32_t)(r * SW + c8) * 2, g_Wh + go);
    }
}

// ---------------- prep: W fp16 row-major images ----------------
__global__ __launch_bounds__(256) void prep_w(const float* __restrict__ W1,
                                              const float* __restrict__ W2,
                                              const float* __restrict__ W3) {
    int id = blockIdx.x * 256 + threadIdx.x;   // 131072
    const float* W; int base, l;
    if (id < 32768)      { W = W1; base = 0;     l = id; }
    else if (id < 98304) { W = W2; base = 32768; l = id - 32768; }
    else                 { W = W3; base = 98304; l = id - 98304; }
    g_Wh[base + l] = __float2half_rn(W[l]);
}

// ---------------- one layer (first W block already prefetched) ----------------
template <int FIN, int FOUT, bool ELU, bool LAST, int NEXT_FOUT, int NEXT_WBASE>
__device__ __forceinline__ void layer(char* smem, uint32_t sb, const float* __restrict__ bias,
                                      int wbase, float* __restrict__ outg, int b) {
    const int tid = threadIdx.x, lane = tid & 31, wid = tid >> 5;
    const int wm = wid >> 2, wn = wid & 3;               // 4 x 4 warp grid
    constexpr int NWN = FOUT / 4, NT16 = NWN / 16, NT8 = NWN / 8, KB = FIN / 64;

    float* sBias = (float*)(smem + OFF_BIAS);
    const float* sDinv = (const float*)(smem + OFF_DINV);
    for (int n = tid; n < FOUT; n += 512) sBias[n] = bias[n];

    float acc[2][NT8][4];
#pragma unroll
    for (int m = 0; m < 2; ++m)
#pragma unroll
        for (int i = 0; i < NT8; ++i)
#pragma unroll
            for (int q = 0; q < 4; ++q) acc[m][i][q] = 0.0f;

    // first W block was prefetched by the previous layer (or kernel prologue)
    CP_WAIT0;
    __syncthreads();

    const uint32_t aRow  = (uint32_t)(wm * 32 + (lane & 15));
    const uint32_t aCol8 = (uint32_t)((lane >> 4) * 8);
    const uint32_t bRow  = (uint32_t)((lane & 7) + ((lane >> 3) & 1) * 8);
    const uint32_t bCol8 = (uint32_t)((lane >> 4) * 8);

    for (int kb = 0; kb < KB; ++kb) {
        if (kb + 1 < KB) stageW<FOUT>(sb, tid, wbase, kb + 1, (kb + 1) & 1);
        CP_COMMIT;
        uint32_t wb = sb + OFF_W + (kb & 1) * WBUF;
#pragma unroll
        for (int ks = 0; ks < 4; ++ks) {
            const int k = kb * 4 + ks;
            uint32_t ah[2][4];
#pragma unroll
            for (int m = 0; m < 2; ++m)
                ldsm4(ah[m], sb + OFF_HHI + ((aRow + 16 * m) * SH + k * 16 + aCol8) * 2);
            uint32_t bh[NT16][4];
#pragma unroll
            for (int t = 0; t < NT16; ++t)
                ldsm4t(bh[t], wb + ((ks * 16 + bRow) * SW + wn * NWN + t * 16 + bCol8) * 2);
#pragma unroll
            for (int t = 0; t < NT16; ++t)
#pragma unroll
                for (int m = 0; m < 2; ++m) {
                    mma16816(acc[m][2 * t], ah[m], bh[t][0], bh[t][1]);
                    mma16816(acc[m][2 * t + 1], ah[m], bh[t][2], bh[t][3]);
                }
        }
        CP_WAIT0;
        __syncthreads();
    }

    // prefetch NEXT layer's first W block (both ring buffers idle from here on)
    if constexpr (NEXT_FOUT > 0) {
        stageW<NEXT_FOUT>(sb, tid, NEXT_WBASE, 0, 0);
        CP_COMMIT;
    }

    // ---- epilogue1: write T * dinv_row into H buffer (own column quarter) ----
#pragma unroll
    for (int m = 0; m < 2; ++m) {
        int r0 = wm * 32 + m * 16 + (lane >> 2), r1 = r0 + 8;
        float d0 = sDinv[r0], d1 = sDinv[r1];
#pragma unroll
        for (int i = 0; i < NT8; ++i) {
            int col = wn * NWN + i * 8 + (lane & 3) * 2;
            *(unsigned*)(smem + OFF_HHI + (r0 * SH + col) * 2) =
                pk(acc[m][i][0] * d0, acc[m][i][1] * d0);
            *(unsigned*)(smem + OFF_HHI + (r1 * SH + col) * 2) =
                pk(acc[m][i][2] * d1, acc[m][i][3] * d1);
        }
    }
    // GEMM2's B-reads for quarter wn depend only on epi1 writes of group wn
    GRP_BAR(wn);

    // ---- GEMM2: out = Mask @ T ----
    float ac2[2][NT8][4];
#pragma unroll
    for (int m = 0; m < 2; ++m)
#pragma unroll
        for (int i = 0; i < NT8; ++i)
#pragma unroll
            for (int q = 0; q < 4; ++q) ac2[m][i][q] = 0.0f;

#pragma unroll
    for (int k = 0; k < 8; ++k) {
        uint32_t am[2][4];
#pragma unroll
        for (int m = 0; m < 2; ++m)
            ldsm4(am[m], sb + OFF_MSK + ((aRow + 16 * m) * SM + k * 16 + aCol8) * 2);
        uint32_t th[NT16][4];
#pragma unroll
        for (int t = 0; t < NT16; ++t)
            ldsm4t(th[t], sb + OFF_HHI + ((k * 16 + bRow) * SH + wn * NWN + t * 16 + bCol8) * 2);
#pragma unroll
        for (int t = 0; t < NT16; ++t)
#pragma unroll
            for (int m = 0; m < 2; ++m) {
                mma16816(ac2[m][2 * t], am[m], th[t][0], th[t][1]);
                mma16816(ac2[m][2 * t + 1], am[m], th[t][2], th[t][3]);
            }
    }
    // epi2 overwrites quarter wn of H; its readers (GEMM2) are group wn only
    GRP_BAR(wn);

    // ---- epilogue2: *dinv_i + bias, ELU, write next-H or global out ----
#pragma unroll
    for (int m = 0; m < 2; ++m) {
        int r0 = wm * 32 + m * 16 + (lane >> 2), r1 = r0 + 8;
        float d0 = sDinv[r0], d1 = sDinv[r1];
#pragma unroll
        for (int i = 0; i < NT8; ++i) {
            int col = wn * NWN + i * 8 + (lane & 3) * 2;
            float b0v = sBias[col], b1v = sBias[col + 1];
            float v00 = fmaf(ac2[m][i][0], d0, b0v), v01 = fmaf(ac2[m][i][1], d0, b1v);
            float v10 = fmaf(ac2[m][i][2], d1, b0v), v11 = fmaf(ac2[m][i][3], d1, b1v);
            if (ELU) {
                v00 = v00 > 0.f ? v00 : elu_neg(v00);
                v01 = v01 > 0.f ? v01 : elu_neg(v01);
                v10 = v10 > 0.f ? v10 : elu_neg(v10);
                v11 = v11 > 0.f ? v11 : elu_neg(v11);
            }
            if (LAST) {
                *(float2*)(outg + ((size_t)b * 128 + r0) * 128 + col) = make_float2(v00, v01);
                *(float2*)(outg + ((size_t)b * 128 + r1) * 128 + col) = make_float2(v10, v11);
            } else {
                *(unsigned*)(smem + OFF_HHI + (r0 * SH + col) * 2) = pk(v00, v01);
                *(unsigned*)(smem + OFF_HHI + (r1 * SH + col) * 2) = pk(v10, v11);
            }
        }
    }
    __syncthreads();   // next layer's GEMM1 reads all of H
}

// ---------------- fused kernel ----------------
__global__ void __launch_bounds__(512, 1) gcn_fused(
    const float* __restrict__ x, const float* __restrict__ adj,
    const float* __restrict__ b1, const float* __restrict__ b2,
    const float* __restrict__ b3, float* __restrict__ out) {
    extern __shared__ char smem[];
    const uint32_t sb = s2u(smem);
    const int b = blockIdx.x, tid = threadIdx.x;
    const int warp = tid >> 5, lane = tid & 31;

    // prefetch layer-1's first W block under the whole prologue
    stageW<256>(sb, tid, 0, 0, 0);
    CP_COMMIT;

    // build dinv + fp16 mask matrix (layer-invariant) straight from ballots
    float* sDinv = (float*)(smem + OFF_DINV);
    const float* ab = adj + (size_t)b * 16384;
    for (int r = warp; r < 128; r += 16) {
        const float* a = ab + r * 128;
        unsigned m[4]; int deg = 0;
#pragma unroll
        for (int s = 0; s < 4; ++s) {
            unsigned w = __ballot_sync(0xffffffffu, a[lane + 32 * s] != 0.0f);
            if (s == (r >> 5)) w |= 1u << (r & 31);
            m[s] = w; deg += __popc(w);
        }
        if (lane == 0) sDinv[r] = rsqrtf((float)deg);
        unsigned w = m[lane >> 3];
        int s4 = (lane & 7) * 4;
        unsigned u0 = (((w >> s4) & 1u) ? 0x3C00u : 0u) | (((w >> (s4 + 1)) & 1u) ? 0x3C000000u : 0u);
        unsigned u1 = (((w >> (s4 + 2)) & 1u) ? 0x3C00u : 0u) | (((w >> (s4 + 3)) & 1u) ? 0x3C000000u : 0u);
        *(uint2*)(smem + OFF_MSK + (r * SM + lane * 4) * 2) = make_uint2(u0, u1);
    }

    // stage x as fp16
    const float* xb = x + (size_t)b * 16384;
    for (int idx = tid; idx < 8192; idx += 512) {
        int r = idx >> 6, c2 = (idx & 63) * 2;
        *(unsigned*)(smem + OFF_HHI + (r * SH + c2) * 2) =
            pk(xb[r * 128 + c2], xb[r * 128 + c2 + 1]);
    }
    __syncthreads();

    layer<128, 256, true,  false, 256, 32768>(smem, sb, b1, 0,     out, b);
    layer<256, 256, true,  false, 128, 98304>(smem, sb, b2, 32768, out, b);
    layer<256, 128, false, true,  0,   0    >(smem, sb, b3, 98304, out, b);
}

// ---------------------------------------------------------------------------
extern "C" void kernel_launch(void* const* d_in, const int* in_sizes, int n_in,
                              void* d_out, int out_size) {
    const float* x   = (const float*)d_in[0];
    const float* adj = (const float*)d_in[1];
    const float* W1  = (const float*)d_in[2];
    const float* b1  = (const float*)d_in[3];
    const float* W2  = (const float*)d_in[4];
    const float* b2  = (const float*)d_in[5];
    const float* W3  = (const float*)d_in[6];
    const float* b3  = (const float*)d_in[7];
    float* out = (float*)d_out;

    cudaFuncSetAttribute(gcn_fused, cudaFuncAttributeMaxDynamicSharedMemorySize, SMEM_SZ);
    prep_w<<<512, 256>>>(W1, W2, W3);
    gcn_fused<<<NB, 512, SMEM_SZ>>>(x, adj, b1, b2, b3, out);
}